// round 13
// baseline (speedup 1.0000x reference)
#include <cuda_runtime.h>
#include <cstdint>

// Problem constants
constexpr int C  = 128;
constexpr int CF = 16;
constexpr int N  = 256;
constexpr int K  = 15;

// ---------------- global scratch (static __device__ — no runtime alloc) ----
__device__ float         g_feat[196 * 256 * 20];   // pre-norm feats (+grid, pads)
__device__ float         g_xnf [196 * 256 * 20];   // normalized feats
__device__ double        g_invn[196 * 256];        // fp64 1/norm
__device__ float         g_w   [196 * 256 * 16];   // softmax weights (15 + pad)
__device__ unsigned char g_rows[196 * 256 * 16];   // neighbor rows  (15 + pad)

// monotone float<->u32 (order-preserving)
__device__ __forceinline__ uint32_t fmono(float f) {
    uint32_t b = __float_as_uint(f);
    return (b & 0x80000000u) ? ~b : (b | 0x80000000u);
}
// monotone double<->u64
__device__ __forceinline__ uint64_t dmono(double d) {
    uint64_t b = (uint64_t)__double_as_longlong(d);
    return (b & 0x8000000000000000ull) ? ~b : (b | 0x8000000000000000ull);
}
__device__ __forceinline__ double dunmono(uint64_t u) {
    uint64_t b = (u & 0x8000000000000000ull) ? (u & 0x7FFFFFFFFFFFFFFFull) : ~u;
    return __longlong_as_double((long long)b);
}

// staging swizzle: conflict-free for channel-lane writes AND pixel-lane reads
__device__ __forceinline__ int stg_off(int c, int px) {
    return c * 64 + ((px + (c >> 2) + 8 * (c & 3)) & 63);
}

// ============================ K1: features =================================
// grid 196, TPB 1024. Cooperative coalesced tile load into smem (K3 pattern),
// float4-smem conv (R11 arithmetic — bitwise-identical features), fp64 norm,
// coalesced float4 flush of both feature arrays to scratch.
constexpr int XO_PITCH = 132;
constexpr int K1_OFF_XO = 0;                        // 256*132*4 = 135168
constexpr int K1_OFF_FW = 135168;                   // 8192
constexpr int K1_OFF_FB = 143360;                   // 64
constexpr int K1_OFF_EX = 143424;                   // 256*20*4 = 20480 (pre-norm)
constexpr int K1_OFF_XS = 163904;                   // 20480 (normalized)
constexpr int K1_SMEM   = 184384;

__global__ void __launch_bounds__(1024, 1)
k1_features(const float* __restrict__ x_in,
            const float* __restrict__ f_w,
            const float* __restrict__ f_b)
{
    extern __shared__ char smraw[];
    float* xo = reinterpret_cast<float*>(smraw + K1_OFF_XO);  // [256][132]
    float* fw = reinterpret_cast<float*>(smraw + K1_OFF_FW);  // [16][128]
    float* fb = reinterpret_cast<float*>(smraw + K1_OFF_FB);  // [16]
    float* ex = reinterpret_cast<float*>(smraw + K1_OFF_EX);  // [256][20] pre-norm
    float* xs = reinterpret_cast<float*>(smraw + K1_OFF_XS);  // [256][20] normalized

    const int p   = blockIdx.x;
    const int b   = p / 49;
    const int wg  = (p / 7) % 7;
    const int hg  = p % 7;
    const int tid = threadIdx.x;
    const int n   = tid & 255;     // pixel
    const int q   = tid >> 8;      // quarter (0..3)
    const int gbase = ((b * C * 112) + wg * 16) * 112 + hg * 16;

    // ---- cooperative loads: weights + patch tile (coalesced, MLP-rich) ----
    for (int idx = tid; idx < CF * C; idx += 1024) fw[idx] = f_w[idx];
    if (tid < CF) fb[tid] = f_b[tid];
    for (int idx = tid; idx < C * N; idx += 1024) {
        int c = idx >> 8;
        int nn = idx & 255;
        int i = nn >> 4, j = nn & 15;
        xo[nn * XO_PITCH + c] = x_in[gbase + c * 12544 + i * 112 + j];
    }
    __syncthreads();

    // ---- conv: thread (n,q) computes channels q*4..q*4+3 (R11 arithmetic) ----
    {
        float a0 = 0.f, a1 = 0.f, a2 = 0.f, a3 = 0.f;
        const float4* xr4 = reinterpret_cast<const float4*>(xo + n * XO_PITCH);
        const float*  fwq = fw + (q * 4) * C;
        #pragma unroll 8
        for (int c4 = 0; c4 < 32; ++c4) {
            float4 xv = xr4[c4];
            float4 w0 = *reinterpret_cast<const float4*>(fwq +         c4 * 4);
            float4 w1 = *reinterpret_cast<const float4*>(fwq + C     + c4 * 4);
            float4 w2 = *reinterpret_cast<const float4*>(fwq + 2 * C + c4 * 4);
            float4 w3 = *reinterpret_cast<const float4*>(fwq + 3 * C + c4 * 4);
            a0 = __fmaf_rn(xv.x, w0.x, a0); a0 = __fmaf_rn(xv.y, w0.y, a0);
            a0 = __fmaf_rn(xv.z, w0.z, a0); a0 = __fmaf_rn(xv.w, w0.w, a0);
            a1 = __fmaf_rn(xv.x, w1.x, a1); a1 = __fmaf_rn(xv.y, w1.y, a1);
            a1 = __fmaf_rn(xv.z, w1.z, a1); a1 = __fmaf_rn(xv.w, w1.w, a1);
            a2 = __fmaf_rn(xv.x, w2.x, a2); a2 = __fmaf_rn(xv.y, w2.y, a2);
            a2 = __fmaf_rn(xv.z, w2.z, a2); a2 = __fmaf_rn(xv.w, w2.w, a2);
            a3 = __fmaf_rn(xv.x, w3.x, a3); a3 = __fmaf_rn(xv.y, w3.y, a3);
            a3 = __fmaf_rn(xv.z, w3.z, a3); a3 = __fmaf_rn(xv.w, w3.w, a3);
        }
        float4 o;
        o.x = __fadd_rn(a0, fb[q * 4 + 0]);
        o.y = __fadd_rn(a1, fb[q * 4 + 1]);
        o.z = __fadd_rn(a2, fb[q * 4 + 2]);
        o.w = __fadd_rn(a3, fb[q * 4 + 3]);
        *reinterpret_cast<float4*>(ex + n * 20 + q * 4) = o;
    }
    __syncthreads();

    // ---- norm (q==0): fp64-exact inverse norm; fp32 normalized into xs ----
    if (q == 0) {
        const int i = n >> 4, j = n & 15;
        const float sd    = __fsqrt_rn(__fdiv_rn(5440.0f, 255.0f));
        const float denom = __fadd_rn(sd, 1e-5f);
        const float g0 = __fdiv_rn((float)i - 7.5f, denom);
        const float g1 = __fdiv_rn((float)j - 7.5f, denom);
        float* ar = ex + n * 20;
        ar[16] = g0; ar[17] = g1; ar[18] = 0.f; ar[19] = 0.f;

        double ss = 0.0;
        #pragma unroll
        for (int d = 0; d < CF; ++d) ss = fma((double)ar[d], (double)ar[d], ss);
        ss = fma((double)g0, (double)g0, ss);
        ss = fma((double)g1, (double)g1, ss);
        double nd = sqrt(ss);
        if (nd < 1e-8) nd = 1e-8;
        double inv = 1.0 / nd;
        g_invn[p * 256 + n] = inv;
        const float rinv = (float)inv;

        float* xw = xs + n * 20;
        #pragma unroll
        for (int d = 0; d < 18; ++d) xw[d] = ar[d] * rinv;
        xw[18] = 0.f; xw[19] = 0.f;
    }
    __syncthreads();

    // ---- coalesced float4 flush of both feature arrays to scratch ----
    {
        const float4* ex4 = reinterpret_cast<const float4*>(ex);
        const float4* xs4 = reinterpret_cast<const float4*>(xs);
        float4* gf4 = reinterpret_cast<float4*>(g_feat + p * 5120);
        float4* gx4 = reinterpret_cast<float4*>(g_xnf  + p * 5120);
        for (int idx = tid; idx < 1280; idx += 1024) {
            gf4[idx] = ex4[idx];
            gx4[idx] = xs4[idx];
        }
    }
}

// ============================ K2: edges ====================================
// grid 784 (patch-quarter of 64 rows), TPB 512, thread = (e 0..7, rr 0..63).
constexpr int K2_OFF_XNF = 0;                        // 256*20*4 = 20480
constexpr int K2_OFF_ACC = 20480;                    // 20480
constexpr int K2_OFF_INV = 40960;                    // 256*8 = 2048
constexpr int K2_OFF_BUF = 43008;                    // 8*64*17*4 = 34816 (u64-aligned)
constexpr int K2_OFF_CAND = 77824;                   // 64*20 = 1280
constexpr int K2_SMEM = 79104;

__global__ void __launch_bounds__(512, 2)
k2_edges(const float* __restrict__ edge_alpha,
         const float* __restrict__ edge_beta)
{
    extern __shared__ char smraw[];
    float*    xnf  = reinterpret_cast<float*>(smraw + K2_OFF_XNF);   // [256][20]
    float*    accf = reinterpret_cast<float*>(smraw + K2_OFF_ACC);   // [256][20]
    double*   invd = reinterpret_cast<double*>(smraw + K2_OFF_INV);  // [256]
    uint32_t* bufU = reinterpret_cast<uint32_t*>(smraw + K2_OFF_BUF);// [8][64][17]
    uint64_t* simk = reinterpret_cast<uint64_t*>(smraw + K2_OFF_BUF);// [64][18] (reuse)
    uint8_t*  cand = reinterpret_cast<uint8_t*>(smraw + K2_OFF_CAND);// [64][20]

    const int pp   = blockIdx.x >> 2;
    const int rblk = blockIdx.x & 3;
    const int tid  = threadIdx.x;
    const int rr   = tid & 63;       // row within quarter
    const int e    = tid >> 6;       // candidate-block id (0..7)
    const int n    = rblk * 64 + rr; // row within patch

    // load patch features from scratch (coalesced float4)
    {
        const float4* gx4 = reinterpret_cast<const float4*>(g_xnf  + pp * 5120);
        const float4* gf4 = reinterpret_cast<const float4*>(g_feat + pp * 5120);
        float4* sx4 = reinterpret_cast<float4*>(xnf);
        float4* sa4 = reinterpret_cast<float4*>(accf);
        for (int idx = tid; idx < 1280; idx += 512) { sx4[idx] = gx4[idx]; sa4[idx] = gf4[idx]; }
        if (tid < 256) invd[tid] = g_invn[pp * 256 + tid];
    }
    __syncthreads();

    // ---- pass 1: row n vs candidates [e*32, e*32+32), packed top-16 ----
    {
        float rreg[18];
        const float* xr = xnf + n * 20;
        #pragma unroll
        for (int d = 0; d < 18; ++d) rreg[d] = xr[d];

        uint32_t kb[16];
        #pragma unroll
        for (int k = 0; k < 16; ++k) kb[k] = 0;

        const int mbase = e * 32;
        for (int mm = 0; mm < 32; ++mm) {
            const int m = mbase + mm;
            const float4* xm4 = reinterpret_cast<const float4*>(xnf + m * 20);
            float4 v0 = xm4[0], v1 = xm4[1], v2 = xm4[2], v3 = xm4[3];  // broadcast
            float2 v4 = *reinterpret_cast<const float2*>(xnf + m * 20 + 16);
            float s0 = 0.f, s1 = 0.f, s2 = 0.f, s3 = 0.f;
            s0 = __fmaf_rn(rreg[0],  v0.x, s0); s1 = __fmaf_rn(rreg[1],  v0.y, s1);
            s2 = __fmaf_rn(rreg[2],  v0.z, s2); s3 = __fmaf_rn(rreg[3],  v0.w, s3);
            s0 = __fmaf_rn(rreg[4],  v1.x, s0); s1 = __fmaf_rn(rreg[5],  v1.y, s1);
            s2 = __fmaf_rn(rreg[6],  v1.z, s2); s3 = __fmaf_rn(rreg[7],  v1.w, s3);
            s0 = __fmaf_rn(rreg[8],  v2.x, s0); s1 = __fmaf_rn(rreg[9],  v2.y, s1);
            s2 = __fmaf_rn(rreg[10], v2.z, s2); s3 = __fmaf_rn(rreg[11], v2.w, s3);
            s0 = __fmaf_rn(rreg[12], v3.x, s0); s1 = __fmaf_rn(rreg[13], v3.y, s1);
            s2 = __fmaf_rn(rreg[14], v3.z, s2); s3 = __fmaf_rn(rreg[15], v3.w, s3);
            s0 = __fmaf_rn(rreg[16], v4.x, s0); s1 = __fmaf_rn(rreg[17], v4.y, s1);
            float s = __fadd_rn(__fadd_rn(s0, s1), __fadd_rn(s2, s3));

            uint32_t key = (fmono(s) & 0xFFFFFF00u) | (uint32_t)(255 - m);
            if (key > kb[15]) {
                uint32_t v = key;
                #pragma unroll
                for (int k = 0; k < 16; ++k) {
                    uint32_t mx = (v > kb[k]) ? v : kb[k];
                    uint32_t mn = (v > kb[k]) ? kb[k] : v;
                    kb[k] = mx; v = mn;
                }
            }
        }
        uint32_t* br = bufU + e * (64 * 17) + rr * 17;
        #pragma unroll
        for (int k = 0; k < 16; ++k) br[k] = kb[k];
    }
    __syncthreads();

    // ---- stage A (e<4): merge blocks (2e,2e+1) -> top-16 into slot 2e ----
    if (e < 4) {
        const uint32_t* pa = bufU + (2 * e)     * (64 * 17) + rr * 17;
        const uint32_t* pb = bufU + (2 * e + 1) * (64 * 17) + rr * 17;
        uint32_t outk[16];
        int ia = 0, ib = 0;
        #pragma unroll
        for (int k = 0; k < 16; ++k) {          // ia,ib <= 15
            uint32_t va = pa[ia], vb = pb[ib];
            bool ta = (va >= vb);
            outk[k] = ta ? va : vb;
            ia += ta; ib += !ta;
        }
        uint32_t* po = bufU + (2 * e) * (64 * 17) + rr * 17;
        #pragma unroll
        for (int k = 0; k < 16; ++k) po[k] = outk[k];
    }
    __syncthreads();

    // ---- stage B (e<2): merge slots (4e, 4e+2) -> top-17 into slot 4e ----
    if (e < 2) {
        const uint32_t* pa = bufU + (4 * e)     * (64 * 17) + rr * 17;
        const uint32_t* pb = bufU + (4 * e + 2) * (64 * 17) + rr * 17;
        uint32_t outk[17];
        int ia = 0, ib = 0;
        #pragma unroll
        for (int k = 0; k < 17; ++k) {
            uint32_t va = (ia < 16) ? pa[ia] : 0u;
            uint32_t vb = (ib < 16) ? pb[ib] : 0u;
            bool ta = (va >= vb);
            outk[k] = ta ? va : vb;
            ia += ta; ib += !ta;
        }
        uint32_t* po = bufU + (4 * e) * (64 * 17) + rr * 17;
        #pragma unroll
        for (int k = 0; k < 17; ++k) po[k] = outk[k];
    }
    __syncthreads();

    // ---- stage C (e==0): merge slots (0,4) -> 18-candidate superset ----
    if (e == 0) {
        const uint32_t* pa = bufU + 0 * (64 * 17) + rr * 17;
        const uint32_t* pb = bufU + 4 * (64 * 17) + rr * 17;
        uint8_t outc[18];
        int ia = 0, ib = 0;
        #pragma unroll
        for (int k = 0; k < 18; ++k) {
            uint32_t va = (ia < 17) ? pa[ia] : 0u;
            uint32_t vb = (ib < 17) ? pb[ib] : 0u;
            bool ta = (va >= vb);
            uint32_t v = ta ? va : vb;
            outc[k] = (uint8_t)(255u - (v & 0xFFu));
            ia += ta; ib += !ta;
        }
        uint8_t* cr = cand + rr * 20;
        #pragma unroll
        for (int k = 0; k < 18; ++k) cr[k] = outc[k];
    }
    __syncthreads();   // bufU dead; simk region live

    // ---- df64 rerank: threads e<6 do candidates e*3..e*3+2 ----
    if (e < 6) {
        float ra[20];
        {
            const float4* ar4 = reinterpret_cast<const float4*>(accf + n * 20);
            #pragma unroll
            for (int qq = 0; qq < 5; ++qq)
                reinterpret_cast<float4*>(ra)[qq] = ar4[qq];
        }
        const double inv_n = invd[n];
        const uint8_t* cr = cand + rr * 20;

        #pragma unroll
        for (int tt = 0; tt < 3; ++tt) {
            const int t = e * 3 + tt;
            const int m = (int)cr[t];
            float am[20];
            {
                const float4* am4 = reinterpret_cast<const float4*>(accf + m * 20);
                #pragma unroll
                for (int qq = 0; qq < 5; ++qq)
                    reinterpret_cast<float4*>(am)[qq] = am4[qq];
            }
            // Dot2 (compensated fp32 dot)
            float sh = 0.0f, sl = 0.0f;
            #pragma unroll
            for (int d = 0; d < 18; ++d) {
                float av = ra[d], bv = am[d];
                float ph = __fmul_rn(av, bv);
                float pl = __fmaf_rn(av, bv, -ph);
                float t1 = __fadd_rn(sh, ph);
                float zz = __fsub_rn(t1, sh);
                float ee = __fadd_rn(__fsub_rn(sh, __fsub_rn(t1, zz)),
                                     __fsub_rn(ph, zz));
                sh = t1;
                sl = __fadd_rn(sl, __fadd_rn(ee, pl));
            }
            double sim = ((double)sh + (double)sl) * inv_n * invd[m];
            simk[rr * 18 + t] = (dmono(sim) & ~0xFFull) | (uint64_t)(255 - m);
        }
    }
    __syncthreads();

    // ---- top-15 select + sigmoid/softmax (e==0) ----
    if (e == 0) {
        const uint64_t* sr = simk + rr * 18;
        uint64_t top[K];
        #pragma unroll
        for (int k = 0; k < K; ++k) top[k] = 0;
        #pragma unroll
        for (int t = 0; t < 18; ++t) {
            uint64_t u = sr[t];
            if (u > top[K - 1]) {
                #pragma unroll
                for (int k = 0; k < K; ++k) {
                    uint64_t mx = (u > top[k]) ? u : top[k];
                    uint64_t mn = (u > top[k]) ? top[k] : u;
                    top[k] = mx; u = mn;
                }
            }
        }
        float sims[K]; int rows[K];
        #pragma unroll
        for (int k = 0; k < K; ++k) {
            rows[k] = 255 - (int)(top[k] & 0xFFull);
            sims[k] = (float)dunmono((top[k] & ~0xFFull) | 0x80ull);
        }

        const float alpha = edge_alpha[0];
        const float beta  = edge_beta[0];
        float wn_[K];
        float wmax = -1e30f;
        #pragma unroll
        for (int k = 0; k < K; ++k) {
            float z  = __fadd_rn(beta, __fmul_rn(alpha, sims[k]));
            float wv = __fdiv_rn(1.0f, __fadd_rn(1.0f, expf(-z)));
            wn_[k] = wv;
            wmax = fmaxf(wmax, wv);
        }
        float wsum = 0.0f;
        #pragma unroll
        for (int k = 0; k < K; ++k) {
            wn_[k] = expf(__fadd_rn(wn_[k], -wmax));
            wsum = __fadd_rn(wsum, wn_[k]);
        }
        float*         wp = g_w    + (pp * 256 + n) * 16;
        unsigned char* rp = g_rows + (pp * 256 + n) * 16;
        #pragma unroll
        for (int k = 0; k < K; ++k) {
            wp[k] = __fdiv_rn(wn_[k], wsum);
            rp[k] = (unsigned char)rows[k];
        }
        wp[15] = 0.f; rp[15] = 0;
    }
}

// ============================ K3: gather ===================================
constexpr int K3_OFF_XO  = 0;                       // 256*132*4 = 135168
constexpr int K3_OFF_WR  = 135168;                  // 256*16*4  = 16384
constexpr int K3_OFF_RW  = 151552;                  // 256*16    = 4096
constexpr int K3_OFF_STG = 155648;                  // 128*64*4  = 32768
constexpr int K3_SMEM = 188416;

__global__ void __launch_bounds__(1024, 1)
k3_gather(const float* __restrict__ x_in, float* __restrict__ out)
{
    extern __shared__ char smraw[];
    float*    xo = reinterpret_cast<float*>(smraw + K3_OFF_XO);   // [256][132]
    float*    wr = reinterpret_cast<float*>(smraw + K3_OFF_WR);   // [256][16]
    uint8_t*  rw = reinterpret_cast<uint8_t*>(smraw + K3_OFF_RW); // [256][16]
    float*    stg = reinterpret_cast<float*>(smraw + K3_OFF_STG); // [128][64]

    const int p   = blockIdx.x;
    const int b   = p / 49;
    const int wg  = (p / 7) % 7;
    const int hg  = p % 7;
    const int tid = threadIdx.x;
    const int gbase = ((b * C * 112) + wg * 16) * 112 + hg * 16;

    // load patch tile + weights/rows
    for (int idx = tid; idx < C * N; idx += 1024) {
        int c = idx >> 8;
        int nn = idx & 255;
        int i = nn >> 4, j = nn & 15;
        xo[nn * XO_PITCH + c] = x_in[gbase + c * 12544 + i * 112 + j];
    }
    for (int idx = tid; idx < 4096; idx += 1024) wr[idx] = g_w[p * 4096 + idx];
    {
        const uint32_t* gr32 = reinterpret_cast<const uint32_t*>(g_rows);
        uint32_t* rw32 = reinterpret_cast<uint32_t*>(rw);
        if (tid < 1024) rw32[tid] = gr32[p * 1024 + tid];
    }
    __syncthreads();

    const int wid  = tid >> 5;
    const int lane = tid & 31;
    const float4* xo4 = reinterpret_cast<const float4*>(xo);

    #pragma unroll 1
    for (int g = 0; g < 4; ++g) {
        #pragma unroll
        for (int px = 0; px < 2; ++px) {
            const int pl = wid * 2 + px;        // 0..63
            const int n2 = g * 64 + pl;
            const float*   wrow = wr + n2 * 16;
            const uint8_t* cr   = rw + n2 * 16;
            float4 o = make_float4(0.f, 0.f, 0.f, 0.f);
            #pragma unroll
            for (int k = 0; k < K; ++k) {
                const float wk  = wrow[k];                   // broadcast
                const int   row = (int)cr[k];                // broadcast
                float4 v = xo4[row * (XO_PITCH / 4) + lane]; // conflict-free
                o.x = __fmaf_rn(wk, v.x, o.x);
                o.y = __fmaf_rn(wk, v.y, o.y);
                o.z = __fmaf_rn(wk, v.z, o.z);
                o.w = __fmaf_rn(wk, v.w, o.w);
            }
            const int c0 = lane * 4;
            stg[stg_off(c0 + 0, pl)] = o.x;
            stg[stg_off(c0 + 1, pl)] = o.y;
            stg[stg_off(c0 + 2, pl)] = o.z;
            stg[stg_off(c0 + 3, pl)] = o.w;
        }
        __syncthreads();
        #pragma unroll
        for (int t = 0; t < 8; ++t) {
            const int idx = t * 1024 + tid;
            const int c  = idx >> 6;
            const int pl = idx & 63;
            const int n2 = g * 64 + pl;
            const int i = n2 >> 4, j = n2 & 15;
            out[gbase + c * 12544 + i * 112 + j] = stg[stg_off(c, pl)];
        }
        __syncthreads();
    }
}

// ============================ launch =======================================
extern "C" void kernel_launch(void* const* d_in, const int* in_sizes, int n_in,
                              void* d_out, int out_size) {
    const float* x_in = (const float*)d_in[0];
    const float* f_w  = (const float*)d_in[1];
    const float* f_b  = (const float*)d_in[2];
    const float* ea   = (const float*)d_in[3];
    const float* eb   = (const float*)d_in[4];
    float* out = (float*)d_out;

    cudaFuncSetAttribute(k1_features,
                         cudaFuncAttributeMaxDynamicSharedMemorySize, K1_SMEM);
    cudaFuncSetAttribute(k2_edges,
                         cudaFuncAttributeMaxDynamicSharedMemorySize, K2_SMEM);
    cudaFuncSetAttribute(k3_gather,
                         cudaFuncAttributeMaxDynamicSharedMemorySize, K3_SMEM);

    k1_features<<<196, 1024, K1_SMEM>>>(x_in, f_w, f_b);
    k2_edges<<<784, 512, K2_SMEM>>>(ea, eb);
    k3_gather<<<196, 1024, K3_SMEM>>>(x_in, out);
}

// round 14
// speedup vs baseline: 1.0855x; 1.0855x over previous
#include <cuda_runtime.h>
#include <cstdint>

// Problem constants
constexpr int C  = 128;
constexpr int CF = 16;
constexpr int N  = 256;
constexpr int K  = 15;

// ---------------- global scratch (static __device__ — no runtime alloc) ----
__device__ float         g_feat[196 * 256 * 20];   // pre-norm feats (+grid, pads)
__device__ float         g_xnf [196 * 256 * 20];   // normalized feats
__device__ double        g_invn[196 * 256];        // fp64 1/norm
__device__ float         g_w   [196 * 256 * 16];   // softmax weights (15 + pad)
__device__ unsigned char g_rows[196 * 256 * 16];   // neighbor rows  (15 + pad)

// monotone float<->u32 (order-preserving)
__device__ __forceinline__ uint32_t fmono(float f) {
    uint32_t b = __float_as_uint(f);
    return (b & 0x80000000u) ? ~b : (b | 0x80000000u);
}
// monotone double<->u64
__device__ __forceinline__ uint64_t dmono(double d) {
    uint64_t b = (uint64_t)__double_as_longlong(d);
    return (b & 0x8000000000000000ull) ? ~b : (b | 0x8000000000000000ull);
}
__device__ __forceinline__ double dunmono(uint64_t u) {
    uint64_t b = (u & 0x8000000000000000ull) ? (u & 0x7FFFFFFFFFFFFFFFull) : ~u;
    return __longlong_as_double((long long)b);
}

// staging swizzle: conflict-free for channel-lane writes AND pixel-lane reads
__device__ __forceinline__ int stg_off(int c, int px) {
    return c * 64 + ((px + (c >> 2) + 8 * (c & 3)) & 63);
}

// ============================ K1: features =================================
// grid 784 (quarter-patch = 64 pixels), TPB 256, 4 CTAs/SM.
// Conv arithmetic identical to R11/R13 (bitwise-identical features).
// Norm: fp64 1/sqrt via fp32-seeded Newton (2 iters, ~1e-16) — much cheaper
// than software sqrt.f64 + div.f64; selection unaffected (tie scale ~1e-7).
constexpr int XO_PITCH  = 132;
constexpr int K1_OFF_XO = 0;                        // 64*132*4 = 33792
constexpr int K1_OFF_FW = 33792;                    // 8192
constexpr int K1_OFF_FB = 41984;                    // 64
constexpr int K1_OFF_EX = 42048;                    // 64*20*4 = 5120 (pre-norm)
constexpr int K1_OFF_XS = 47168;                    // 5120 (normalized)
constexpr int K1_SMEM   = 52288;

__global__ void __launch_bounds__(256, 4)
k1_features(const float* __restrict__ x_in,
            const float* __restrict__ f_w,
            const float* __restrict__ f_b)
{
    extern __shared__ char smraw[];
    float* xo = reinterpret_cast<float*>(smraw + K1_OFF_XO);  // [64][132]
    float* fw = reinterpret_cast<float*>(smraw + K1_OFF_FW);  // [16][128]
    float* fb = reinterpret_cast<float*>(smraw + K1_OFF_FB);  // [16]
    float* ex = reinterpret_cast<float*>(smraw + K1_OFF_EX);  // [64][20] pre-norm
    float* xs = reinterpret_cast<float*>(smraw + K1_OFF_XS);  // [64][20] normalized

    const int pp   = blockIdx.x >> 2;   // patch
    const int rblk = blockIdx.x & 3;    // quarter (64 pixels)
    const int b   = pp / 49;
    const int wg  = (pp / 7) % 7;
    const int hg  = pp % 7;
    const int tid = threadIdx.x;
    const int nn  = tid & 63;           // local pixel 0..63
    const int q   = tid >> 6;           // channel quarter 0..3
    const int gbase = ((b * C * 112) + wg * 16) * 112 + hg * 16;

    // ---- cooperative loads: weights + 64-pixel tile slice (coalesced) ----
    for (int idx = tid; idx < CF * C; idx += 256) fw[idx] = f_w[idx];
    if (tid < CF) fb[tid] = f_b[tid];
    for (int idx = tid; idx < C * 64; idx += 256) {
        int c  = idx >> 6;
        int ll = idx & 63;
        int n  = rblk * 64 + ll;        // global pixel in patch
        int i = n >> 4, j = n & 15;
        xo[ll * XO_PITCH + c] = x_in[gbase + c * 12544 + i * 112 + j];
    }
    __syncthreads();

    // ---- conv: thread (nn,q) computes channels q*4..q*4+3 (R11 arithmetic) ----
    {
        float a0 = 0.f, a1 = 0.f, a2 = 0.f, a3 = 0.f;
        const float4* xr4 = reinterpret_cast<const float4*>(xo + nn * XO_PITCH);
        const float*  fwq = fw + (q * 4) * C;
        #pragma unroll 8
        for (int c4 = 0; c4 < 32; ++c4) {
            float4 xv = xr4[c4];
            float4 w0 = *reinterpret_cast<const float4*>(fwq +         c4 * 4);
            float4 w1 = *reinterpret_cast<const float4*>(fwq + C     + c4 * 4);
            float4 w2 = *reinterpret_cast<const float4*>(fwq + 2 * C + c4 * 4);
            float4 w3 = *reinterpret_cast<const float4*>(fwq + 3 * C + c4 * 4);
            a0 = __fmaf_rn(xv.x, w0.x, a0); a0 = __fmaf_rn(xv.y, w0.y, a0);
            a0 = __fmaf_rn(xv.z, w0.z, a0); a0 = __fmaf_rn(xv.w, w0.w, a0);
            a1 = __fmaf_rn(xv.x, w1.x, a1); a1 = __fmaf_rn(xv.y, w1.y, a1);
            a1 = __fmaf_rn(xv.z, w1.z, a1); a1 = __fmaf_rn(xv.w, w1.w, a1);
            a2 = __fmaf_rn(xv.x, w2.x, a2); a2 = __fmaf_rn(xv.y, w2.y, a2);
            a2 = __fmaf_rn(xv.z, w2.z, a2); a2 = __fmaf_rn(xv.w, w2.w, a2);
            a3 = __fmaf_rn(xv.x, w3.x, a3); a3 = __fmaf_rn(xv.y, w3.y, a3);
            a3 = __fmaf_rn(xv.z, w3.z, a3); a3 = __fmaf_rn(xv.w, w3.w, a3);
        }
        float4 o;
        o.x = __fadd_rn(a0, fb[q * 4 + 0]);
        o.y = __fadd_rn(a1, fb[q * 4 + 1]);
        o.z = __fadd_rn(a2, fb[q * 4 + 2]);
        o.w = __fadd_rn(a3, fb[q * 4 + 3]);
        *reinterpret_cast<float4*>(ex + nn * 20 + q * 4) = o;
    }
    __syncthreads();

    // ---- norm (q==0): fp64 1/sqrt via Newton; fp32 normalized into xs ----
    if (q == 0) {
        const int n = rblk * 64 + nn;
        const int i = n >> 4, j = n & 15;
        const float sd    = __fsqrt_rn(__fdiv_rn(5440.0f, 255.0f));
        const float denom = __fadd_rn(sd, 1e-5f);
        const float g0 = __fdiv_rn((float)i - 7.5f, denom);
        const float g1 = __fdiv_rn((float)j - 7.5f, denom);
        float* ar = ex + nn * 20;
        ar[16] = g0; ar[17] = g1; ar[18] = 0.f; ar[19] = 0.f;

        double ss = 0.0;                 // exact fp64 sum of fp32 squares
        #pragma unroll
        for (int d = 0; d < CF; ++d) ss = fma((double)ar[d], (double)ar[d], ss);
        ss = fma((double)g0, (double)g0, ss);
        ss = fma((double)g1, (double)g1, ss);

        // inv = 1/sqrt(ss): fp32 rsqrt seed + 2 Newton iters in fp64 (~1e-16)
        double inv;
        if (ss > 1e-16) {
            double r = (double)rsqrtf((float)ss);
            const double hss = 0.5 * ss;
            r = r * fma(-hss, r * r, 1.5);
            r = r * fma(-hss, r * r, 1.5);
            inv = r;
        } else {
            inv = 1e8;                   // == 1/max(sqrt(ss), 1e-8) for tiny ss
        }
        g_invn[pp * 256 + n] = inv;
        const float rinv = (float)inv;

        float* xw = xs + nn * 20;
        #pragma unroll
        for (int d = 0; d < 18; ++d) xw[d] = ar[d] * rinv;
        xw[18] = 0.f; xw[19] = 0.f;
    }
    __syncthreads();

    // ---- coalesced float4 flush of both feature arrays to scratch ----
    {
        const float4* ex4 = reinterpret_cast<const float4*>(ex);
        const float4* xs4 = reinterpret_cast<const float4*>(xs);
        float4* gf4 = reinterpret_cast<float4*>(g_feat) + pp * 1280 + rblk * 320;
        float4* gx4 = reinterpret_cast<float4*>(g_xnf)  + pp * 1280 + rblk * 320;
        for (int idx = tid; idx < 320; idx += 256) {
            gf4[idx] = ex4[idx];
            gx4[idx] = xs4[idx];
        }
    }
}

// ============================ K2: edges ====================================
// grid 784 (patch-quarter of 64 rows), TPB 512, thread = (e 0..7, rr 0..63).
constexpr int K2_OFF_XNF = 0;                        // 256*20*4 = 20480
constexpr int K2_OFF_ACC = 20480;                    // 20480
constexpr int K2_OFF_INV = 40960;                    // 256*8 = 2048
constexpr int K2_OFF_BUF = 43008;                    // 8*64*17*4 = 34816 (u64-aligned)
constexpr int K2_OFF_CAND = 77824;                   // 64*20 = 1280
constexpr int K2_SMEM = 79104;

__global__ void __launch_bounds__(512, 2)
k2_edges(const float* __restrict__ edge_alpha,
         const float* __restrict__ edge_beta)
{
    extern __shared__ char smraw[];
    float*    xnf  = reinterpret_cast<float*>(smraw + K2_OFF_XNF);   // [256][20]
    float*    accf = reinterpret_cast<float*>(smraw + K2_OFF_ACC);   // [256][20]
    double*   invd = reinterpret_cast<double*>(smraw + K2_OFF_INV);  // [256]
    uint32_t* bufU = reinterpret_cast<uint32_t*>(smraw + K2_OFF_BUF);// [8][64][17]
    uint64_t* simk = reinterpret_cast<uint64_t*>(smraw + K2_OFF_BUF);// [64][18] (reuse)
    uint8_t*  cand = reinterpret_cast<uint8_t*>(smraw + K2_OFF_CAND);// [64][20]

    const int pp   = blockIdx.x >> 2;
    const int rblk = blockIdx.x & 3;
    const int tid  = threadIdx.x;
    const int rr   = tid & 63;       // row within quarter
    const int e    = tid >> 6;       // candidate-block id (0..7)
    const int n    = rblk * 64 + rr; // row within patch

    // load patch features from scratch (coalesced float4)
    {
        const float4* gx4 = reinterpret_cast<const float4*>(g_xnf  + pp * 5120);
        const float4* gf4 = reinterpret_cast<const float4*>(g_feat + pp * 5120);
        float4* sx4 = reinterpret_cast<float4*>(xnf);
        float4* sa4 = reinterpret_cast<float4*>(accf);
        for (int idx = tid; idx < 1280; idx += 512) { sx4[idx] = gx4[idx]; sa4[idx] = gf4[idx]; }
        if (tid < 256) invd[tid] = g_invn[pp * 256 + tid];
    }
    __syncthreads();

    // ---- pass 1: row n vs candidates [e*32, e*32+32), packed top-16 ----
    {
        float rreg[18];
        const float* xr = xnf + n * 20;
        #pragma unroll
        for (int d = 0; d < 18; ++d) rreg[d] = xr[d];

        uint32_t kb[16];
        #pragma unroll
        for (int k = 0; k < 16; ++k) kb[k] = 0;

        const int mbase = e * 32;
        for (int mm = 0; mm < 32; ++mm) {
            const int m = mbase + mm;
            const float4* xm4 = reinterpret_cast<const float4*>(xnf + m * 20);
            float4 v0 = xm4[0], v1 = xm4[1], v2 = xm4[2], v3 = xm4[3];  // broadcast
            float2 v4 = *reinterpret_cast<const float2*>(xnf + m * 20 + 16);
            float s0 = 0.f, s1 = 0.f, s2 = 0.f, s3 = 0.f;
            s0 = __fmaf_rn(rreg[0],  v0.x, s0); s1 = __fmaf_rn(rreg[1],  v0.y, s1);
            s2 = __fmaf_rn(rreg[2],  v0.z, s2); s3 = __fmaf_rn(rreg[3],  v0.w, s3);
            s0 = __fmaf_rn(rreg[4],  v1.x, s0); s1 = __fmaf_rn(rreg[5],  v1.y, s1);
            s2 = __fmaf_rn(rreg[6],  v1.z, s2); s3 = __fmaf_rn(rreg[7],  v1.w, s3);
            s0 = __fmaf_rn(rreg[8],  v2.x, s0); s1 = __fmaf_rn(rreg[9],  v2.y, s1);
            s2 = __fmaf_rn(rreg[10], v2.z, s2); s3 = __fmaf_rn(rreg[11], v2.w, s3);
            s0 = __fmaf_rn(rreg[12], v3.x, s0); s1 = __fmaf_rn(rreg[13], v3.y, s1);
            s2 = __fmaf_rn(rreg[14], v3.z, s2); s3 = __fmaf_rn(rreg[15], v3.w, s3);
            s0 = __fmaf_rn(rreg[16], v4.x, s0); s1 = __fmaf_rn(rreg[17], v4.y, s1);
            float s = __fadd_rn(__fadd_rn(s0, s1), __fadd_rn(s2, s3));

            uint32_t key = (fmono(s) & 0xFFFFFF00u) | (uint32_t)(255 - m);
            if (key > kb[15]) {
                uint32_t v = key;
                #pragma unroll
                for (int k = 0; k < 16; ++k) {
                    uint32_t mx = (v > kb[k]) ? v : kb[k];
                    uint32_t mn = (v > kb[k]) ? kb[k] : v;
                    kb[k] = mx; v = mn;
                }
            }
        }
        uint32_t* br = bufU + e * (64 * 17) + rr * 17;
        #pragma unroll
        for (int k = 0; k < 16; ++k) br[k] = kb[k];
    }
    __syncthreads();

    // ---- stage A (e<4): merge blocks (2e,2e+1) -> top-16 into slot 2e ----
    if (e < 4) {
        const uint32_t* pa = bufU + (2 * e)     * (64 * 17) + rr * 17;
        const uint32_t* pb = bufU + (2 * e + 1) * (64 * 17) + rr * 17;
        uint32_t outk[16];
        int ia = 0, ib = 0;
        #pragma unroll
        for (int k = 0; k < 16; ++k) {          // ia,ib <= 15
            uint32_t va = pa[ia], vb = pb[ib];
            bool ta = (va >= vb);
            outk[k] = ta ? va : vb;
            ia += ta; ib += !ta;
        }
        uint32_t* po = bufU + (2 * e) * (64 * 17) + rr * 17;
        #pragma unroll
        for (int k = 0; k < 16; ++k) po[k] = outk[k];
    }
    __syncthreads();

    // ---- stage B (e<2): merge slots (4e, 4e+2) -> top-17 into slot 4e ----
    if (e < 2) {
        const uint32_t* pa = bufU + (4 * e)     * (64 * 17) + rr * 17;
        const uint32_t* pb = bufU + (4 * e + 2) * (64 * 17) + rr * 17;
        uint32_t outk[17];
        int ia = 0, ib = 0;
        #pragma unroll
        for (int k = 0; k < 17; ++k) {
            uint32_t va = (ia < 16) ? pa[ia] : 0u;
            uint32_t vb = (ib < 16) ? pb[ib] : 0u;
            bool ta = (va >= vb);
            outk[k] = ta ? va : vb;
            ia += ta; ib += !ta;
        }
        uint32_t* po = bufU + (4 * e) * (64 * 17) + rr * 17;
        #pragma unroll
        for (int k = 0; k < 17; ++k) po[k] = outk[k];
    }
    __syncthreads();

    // ---- stage C (e==0): merge slots (0,4) -> 18-candidate superset ----
    if (e == 0) {
        const uint32_t* pa = bufU + 0 * (64 * 17) + rr * 17;
        const uint32_t* pb = bufU + 4 * (64 * 17) + rr * 17;
        uint8_t outc[18];
        int ia = 0, ib = 0;
        #pragma unroll
        for (int k = 0; k < 18; ++k) {
            uint32_t va = (ia < 17) ? pa[ia] : 0u;
            uint32_t vb = (ib < 17) ? pb[ib] : 0u;
            bool ta = (va >= vb);
            uint32_t v = ta ? va : vb;
            outc[k] = (uint8_t)(255u - (v & 0xFFu));
            ia += ta; ib += !ta;
        }
        uint8_t* cr = cand + rr * 20;
        #pragma unroll
        for (int k = 0; k < 18; ++k) cr[k] = outc[k];
    }
    __syncthreads();   // bufU dead; simk region live

    // ---- df64 rerank: threads e<6 do candidates e*3..e*3+2 ----
    if (e < 6) {
        float ra[20];
        {
            const float4* ar4 = reinterpret_cast<const float4*>(accf + n * 20);
            #pragma unroll
            for (int qq = 0; qq < 5; ++qq)
                reinterpret_cast<float4*>(ra)[qq] = ar4[qq];
        }
        const double inv_n = invd[n];
        const uint8_t* cr = cand + rr * 20;

        #pragma unroll
        for (int tt = 0; tt < 3; ++tt) {
            const int t = e * 3 + tt;
            const int m = (int)cr[t];
            float am[20];
            {
                const float4* am4 = reinterpret_cast<const float4*>(accf + m * 20);
                #pragma unroll
                for (int qq = 0; qq < 5; ++qq)
                    reinterpret_cast<float4*>(am)[qq] = am4[qq];
            }
            // Dot2 (compensated fp32 dot)
            float sh = 0.0f, sl = 0.0f;
            #pragma unroll
            for (int d = 0; d < 18; ++d) {
                float av = ra[d], bv = am[d];
                float ph = __fmul_rn(av, bv);
                float pl = __fmaf_rn(av, bv, -ph);
                float t1 = __fadd_rn(sh, ph);
                float zz = __fsub_rn(t1, sh);
                float ee = __fadd_rn(__fsub_rn(sh, __fsub_rn(t1, zz)),
                                     __fsub_rn(ph, zz));
                sh = t1;
                sl = __fadd_rn(sl, __fadd_rn(ee, pl));
            }
            double sim = ((double)sh + (double)sl) * inv_n * invd[m];
            simk[rr * 18 + t] = (dmono(sim) & ~0xFFull) | (uint64_t)(255 - m);
        }
    }
    __syncthreads();

    // ---- top-15 select + sigmoid/softmax (e==0) ----
    if (e == 0) {
        const uint64_t* sr = simk + rr * 18;
        uint64_t top[K];
        #pragma unroll
        for (int k = 0; k < K; ++k) top[k] = 0;
        #pragma unroll
        for (int t = 0; t < 18; ++t) {
            uint64_t u = sr[t];
            if (u > top[K - 1]) {
                #pragma unroll
                for (int k = 0; k < K; ++k) {
                    uint64_t mx = (u > top[k]) ? u : top[k];
                    uint64_t mn = (u > top[k]) ? top[k] : u;
                    top[k] = mx; u = mn;
                }
            }
        }
        float sims[K]; int rows[K];
        #pragma unroll
        for (int k = 0; k < K; ++k) {
            rows[k] = 255 - (int)(top[k] & 0xFFull);
            sims[k] = (float)dunmono((top[k] & ~0xFFull) | 0x80ull);
        }

        const float alpha = edge_alpha[0];
        const float beta  = edge_beta[0];
        float wn_[K];
        float wmax = -1e30f;
        #pragma unroll
        for (int k = 0; k < K; ++k) {
            float z  = __fadd_rn(beta, __fmul_rn(alpha, sims[k]));
            float wv = __fdiv_rn(1.0f, __fadd_rn(1.0f, expf(-z)));
            wn_[k] = wv;
            wmax = fmaxf(wmax, wv);
        }
        float wsum = 0.0f;
        #pragma unroll
        for (int k = 0; k < K; ++k) {
            wn_[k] = expf(__fadd_rn(wn_[k], -wmax));
            wsum = __fadd_rn(wsum, wn_[k]);
        }
        float*         wp = g_w    + (pp * 256 + n) * 16;
        unsigned char* rp = g_rows + (pp * 256 + n) * 16;
        #pragma unroll
        for (int k = 0; k < K; ++k) {
            wp[k] = __fdiv_rn(wn_[k], wsum);
            rp[k] = (unsigned char)rows[k];
        }
        wp[15] = 0.f; rp[15] = 0;
    }
}

// ============================ K3: gather ===================================
constexpr int K3_OFF_XO  = 0;                       // 256*132*4 = 135168
constexpr int K3_OFF_WR  = 135168;                  // 256*16*4  = 16384
constexpr int K3_OFF_RW  = 151552;                  // 256*16    = 4096
constexpr int K3_OFF_STG = 155648;                  // 128*64*4  = 32768
constexpr int K3_SMEM = 188416;

__global__ void __launch_bounds__(1024, 1)
k3_gather(const float* __restrict__ x_in, float* __restrict__ out)
{
    extern __shared__ char smraw[];
    float*    xo = reinterpret_cast<float*>(smraw + K3_OFF_XO);   // [256][132]
    float*    wr = reinterpret_cast<float*>(smraw + K3_OFF_WR);   // [256][16]
    uint8_t*  rw = reinterpret_cast<uint8_t*>(smraw + K3_OFF_RW); // [256][16]
    float*    stg = reinterpret_cast<float*>(smraw + K3_OFF_STG); // [128][64]

    const int p   = blockIdx.x;
    const int b   = p / 49;
    const int wg  = (p / 7) % 7;
    const int hg  = p % 7;
    const int tid = threadIdx.x;
    const int gbase = ((b * C * 112) + wg * 16) * 112 + hg * 16;

    // load patch tile + weights/rows
    for (int idx = tid; idx < C * N; idx += 1024) {
        int c = idx >> 8;
        int nn = idx & 255;
        int i = nn >> 4, j = nn & 15;
        xo[nn * XO_PITCH + c] = x_in[gbase + c * 12544 + i * 112 + j];
    }
    for (int idx = tid; idx < 4096; idx += 1024) wr[idx] = g_w[p * 4096 + idx];
    {
        const uint32_t* gr32 = reinterpret_cast<const uint32_t*>(g_rows);
        uint32_t* rw32 = reinterpret_cast<uint32_t*>(rw);
        if (tid < 1024) rw32[tid] = gr32[p * 1024 + tid];
    }
    __syncthreads();

    const int wid  = tid >> 5;
    const int lane = tid & 31;
    const float4* xo4 = reinterpret_cast<const float4*>(xo);

    #pragma unroll 1
    for (int g = 0; g < 4; ++g) {
        #pragma unroll
        for (int px = 0; px < 2; ++px) {
            const int pl = wid * 2 + px;        // 0..63
            const int n2 = g * 64 + pl;
            const float*   wrow = wr + n2 * 16;
            const uint8_t* cr   = rw + n2 * 16;
            float4 o = make_float4(0.f, 0.f, 0.f, 0.f);
            #pragma unroll
            for (int k = 0; k < K; ++k) {
                const float wk  = wrow[k];                   // broadcast
                const int   row = (int)cr[k];                // broadcast
                float4 v = xo4[row * (XO_PITCH / 4) + lane]; // conflict-free
                o.x = __fmaf_rn(wk, v.x, o.x);
                o.y = __fmaf_rn(wk, v.y, o.y);
                o.z = __fmaf_rn(wk, v.z, o.z);
                o.w = __fmaf_rn(wk, v.w, o.w);
            }
            const int c0 = lane * 4;
            stg[stg_off(c0 + 0, pl)] = o.x;
            stg[stg_off(c0 + 1, pl)] = o.y;
            stg[stg_off(c0 + 2, pl)] = o.z;
            stg[stg_off(c0 + 3, pl)] = o.w;
        }
        __syncthreads();
        #pragma unroll
        for (int t = 0; t < 8; ++t) {
            const int idx = t * 1024 + tid;
            const int c  = idx >> 6;
            const int pl = idx & 63;
            const int n2 = g * 64 + pl;
            const int i = n2 >> 4, j = n2 & 15;
            out[gbase + c * 12544 + i * 112 + j] = stg[stg_off(c, pl)];
        }
        __syncthreads();
    }
}

// ============================ launch =======================================
extern "C" void kernel_launch(void* const* d_in, const int* in_sizes, int n_in,
                              void* d_out, int out_size) {
    const float* x_in = (const float*)d_in[0];
    const float* f_w  = (const float*)d_in[1];
    const float* f_b  = (const float*)d_in[2];
    const float* ea   = (const float*)d_in[3];
    const float* eb   = (const float*)d_in[4];
    float* out = (float*)d_out;

    cudaFuncSetAttribute(k1_features,
                         cudaFuncAttributeMaxDynamicSharedMemorySize, K1_SMEM);
    cudaFuncSetAttribute(k2_edges,
                         cudaFuncAttributeMaxDynamicSharedMemorySize, K2_SMEM);
    cudaFuncSetAttribute(k3_gather,
                         cudaFuncAttributeMaxDynamicSharedMemorySize, K3_SMEM);

    k1_features<<<784, 256, K1_SMEM>>>(x_in, f_w, f_b);
    k2_edges<<<784, 512, K2_SMEM>>>(ea, eb);
    k3_gather<<<196, 1024, K3_SMEM>>>(x_in, out);
}

// round 15
// speedup vs baseline: 1.1417x; 1.0518x over previous
#include <cuda_runtime.h>
#include <cstdint>

// Problem constants
constexpr int C  = 128;
constexpr int CF = 16;
constexpr int N  = 256;
constexpr int K  = 15;

// ---------------- global scratch (static __device__ — no runtime alloc) ----
__device__ float         g_feat[196 * 256 * 20];   // pre-norm feats (+grid, pads)
__device__ double        g_invn[196 * 256];        // fp64 1/norm
__device__ float         g_w   [196 * 256 * 16];   // softmax weights (15 + pad)
__device__ unsigned char g_rows[196 * 256 * 16];   // neighbor rows  (15 + pad)

// monotone float<->u32 (order-preserving)
__device__ __forceinline__ uint32_t fmono(float f) {
    uint32_t b = __float_as_uint(f);
    return (b & 0x80000000u) ? ~b : (b | 0x80000000u);
}
// monotone double<->u64
__device__ __forceinline__ uint64_t dmono(double d) {
    uint64_t b = (uint64_t)__double_as_longlong(d);
    return (b & 0x8000000000000000ull) ? ~b : (b | 0x8000000000000000ull);
}
__device__ __forceinline__ double dunmono(uint64_t u) {
    uint64_t b = (u & 0x8000000000000000ull) ? (u & 0x7FFFFFFFFFFFFFFFull) : ~u;
    return __longlong_as_double((long long)b);
}

// staging swizzle: conflict-free for channel-lane writes AND pixel-lane reads
__device__ __forceinline__ int stg_off(int c, int px) {
    return c * 64 + ((px + (c >> 2) + 8 * (c & 3)) & 63);
}

// ============================ K1: features =================================
// grid 784 (quarter-patch = 64 pixels), TPB 256, 4 CTAs/SM.
// Conv arithmetic identical to R11-R14 (bitwise-identical features).
constexpr int XO_PITCH  = 132;
constexpr int K1_OFF_XO = 0;                        // 64*132*4 = 33792
constexpr int K1_OFF_FW = 33792;                    // 8192
constexpr int K1_OFF_FB = 41984;                    // 64
constexpr int K1_OFF_EX = 42048;                    // 64*20*4 = 5120 (pre-norm)
constexpr int K1_SMEM   = 47168;

__global__ void __launch_bounds__(256, 4)
k1_features(const float* __restrict__ x_in,
            const float* __restrict__ f_w,
            const float* __restrict__ f_b)
{
    extern __shared__ char smraw[];
    float* xo = reinterpret_cast<float*>(smraw + K1_OFF_XO);  // [64][132]
    float* fw = reinterpret_cast<float*>(smraw + K1_OFF_FW);  // [16][128]
    float* fb = reinterpret_cast<float*>(smraw + K1_OFF_FB);  // [16]
    float* ex = reinterpret_cast<float*>(smraw + K1_OFF_EX);  // [64][20] pre-norm

    const int pp   = blockIdx.x >> 2;   // patch
    const int rblk = blockIdx.x & 3;    // quarter (64 pixels)
    const int b   = pp / 49;
    const int wg  = (pp / 7) % 7;
    const int hg  = pp % 7;
    const int tid = threadIdx.x;
    const int nn  = tid & 63;           // local pixel 0..63
    const int q   = tid >> 6;           // channel quarter 0..3
    const int gbase = ((b * C * 112) + wg * 16) * 112 + hg * 16;

    // ---- cooperative loads: weights + 64-pixel tile slice (coalesced) ----
    for (int idx = tid; idx < CF * C; idx += 256) fw[idx] = f_w[idx];
    if (tid < CF) fb[tid] = f_b[tid];
    for (int idx = tid; idx < C * 64; idx += 256) {
        int c  = idx >> 6;
        int ll = idx & 63;
        int n  = rblk * 64 + ll;        // global pixel in patch
        int i = n >> 4, j = n & 15;
        xo[ll * XO_PITCH + c] = x_in[gbase + c * 12544 + i * 112 + j];
    }
    __syncthreads();

    // ---- conv: thread (nn,q) computes channels q*4..q*4+3 (R11 arithmetic) ----
    {
        float a0 = 0.f, a1 = 0.f, a2 = 0.f, a3 = 0.f;
        const float4* xr4 = reinterpret_cast<const float4*>(xo + nn * XO_PITCH);
        const float*  fwq = fw + (q * 4) * C;
        #pragma unroll 8
        for (int c4 = 0; c4 < 32; ++c4) {
            float4 xv = xr4[c4];
            float4 w0 = *reinterpret_cast<const float4*>(fwq +         c4 * 4);
            float4 w1 = *reinterpret_cast<const float4*>(fwq + C     + c4 * 4);
            float4 w2 = *reinterpret_cast<const float4*>(fwq + 2 * C + c4 * 4);
            float4 w3 = *reinterpret_cast<const float4*>(fwq + 3 * C + c4 * 4);
            a0 = __fmaf_rn(xv.x, w0.x, a0); a0 = __fmaf_rn(xv.y, w0.y, a0);
            a0 = __fmaf_rn(xv.z, w0.z, a0); a0 = __fmaf_rn(xv.w, w0.w, a0);
            a1 = __fmaf_rn(xv.x, w1.x, a1); a1 = __fmaf_rn(xv.y, w1.y, a1);
            a1 = __fmaf_rn(xv.z, w1.z, a1); a1 = __fmaf_rn(xv.w, w1.w, a1);
            a2 = __fmaf_rn(xv.x, w2.x, a2); a2 = __fmaf_rn(xv.y, w2.y, a2);
            a2 = __fmaf_rn(xv.z, w2.z, a2); a2 = __fmaf_rn(xv.w, w2.w, a2);
            a3 = __fmaf_rn(xv.x, w3.x, a3); a3 = __fmaf_rn(xv.y, w3.y, a3);
            a3 = __fmaf_rn(xv.z, w3.z, a3); a3 = __fmaf_rn(xv.w, w3.w, a3);
        }
        float4 o;
        o.x = __fadd_rn(a0, fb[q * 4 + 0]);
        o.y = __fadd_rn(a1, fb[q * 4 + 1]);
        o.z = __fadd_rn(a2, fb[q * 4 + 2]);
        o.w = __fadd_rn(a3, fb[q * 4 + 3]);
        *reinterpret_cast<float4*>(ex + nn * 20 + q * 4) = o;
    }
    __syncthreads();

    // ---- norm (q==0): fp64 1/sqrt via fp32-seeded Newton (2 iters) ----
    if (q == 0) {
        const int n = rblk * 64 + nn;
        const int i = n >> 4, j = n & 15;
        const float sd    = __fsqrt_rn(__fdiv_rn(5440.0f, 255.0f));
        const float denom = __fadd_rn(sd, 1e-5f);
        const float g0 = __fdiv_rn((float)i - 7.5f, denom);
        const float g1 = __fdiv_rn((float)j - 7.5f, denom);
        float* ar = ex + nn * 20;
        ar[16] = g0; ar[17] = g1; ar[18] = 0.f; ar[19] = 0.f;

        double ss = 0.0;                 // exact fp64 sum of fp32 squares
        #pragma unroll
        for (int d = 0; d < CF; ++d) ss = fma((double)ar[d], (double)ar[d], ss);
        ss = fma((double)g0, (double)g0, ss);
        ss = fma((double)g1, (double)g1, ss);

        double inv;
        if (ss > 1e-16) {
            double r = (double)rsqrtf((float)ss);
            const double hss = 0.5 * ss;
            r = r * fma(-hss, r * r, 1.5);
            r = r * fma(-hss, r * r, 1.5);
            inv = r;
        } else {
            inv = 1e8;                   // == 1/max(sqrt(ss), 1e-8) for tiny ss
        }
        g_invn[pp * 256 + n] = inv;
    }
    __syncthreads();

    // ---- coalesced float4 flush of pre-norm feats to scratch ----
    {
        const float4* ex4 = reinterpret_cast<const float4*>(ex);
        float4* gf4 = reinterpret_cast<float4*>(g_feat) + pp * 1280 + rblk * 320;
        for (int idx = tid; idx < 320; idx += 256) gf4[idx] = ex4[idx];
    }
}

// ============================ K2: edges ====================================
// grid 784 (patch-quarter of 64 rows), TPB 256, thread = (e 0..3, rr 0..63).
// 42 KB smem -> 4 CTAs/SM (waves 2.65 -> 1.32 vs R14).
// Pass-1 sims computed from pre-norm feats: s = dot(a_n*rinv_n, a_m)*rinv_m.
// Pass-1 only picks the 18-candidate superset (b>=2 margin); the df64 rerank
// (unchanged) makes the final selection -> output identical.
constexpr int K2_OFF_ACC  = 0;                       // 256*20*4 = 20480
constexpr int K2_OFF_INV  = 20480;                   // 256*8 = 2048 (8B aligned)
constexpr int K2_OFF_INVF = 22528;                   // 256*4 = 1024
constexpr int K2_OFF_BUF  = 23552;                   // 4*64*17*4 = 17408 (8B aligned)
constexpr int K2_OFF_CAND = 40960;                   // 64*20 = 1280
constexpr int K2_SMEM     = 42240;

__global__ void __launch_bounds__(256, 4)
k2_edges(const float* __restrict__ edge_alpha,
         const float* __restrict__ edge_beta)
{
    extern __shared__ char smraw[];
    float*    accf = reinterpret_cast<float*>(smraw + K2_OFF_ACC);   // [256][20]
    double*   invd = reinterpret_cast<double*>(smraw + K2_OFF_INV);  // [256]
    float*    invf = reinterpret_cast<float*>(smraw + K2_OFF_INVF);  // [256]
    uint32_t* bufU = reinterpret_cast<uint32_t*>(smraw + K2_OFF_BUF);// [4][64][17]
    uint64_t* simk = reinterpret_cast<uint64_t*>(smraw + K2_OFF_BUF);// [64][18] (reuse)
    uint8_t*  cand = reinterpret_cast<uint8_t*>(smraw + K2_OFF_CAND);// [64][20]

    const int pp   = blockIdx.x >> 2;
    const int rblk = blockIdx.x & 3;
    const int tid  = threadIdx.x;
    const int rr   = tid & 63;       // row within quarter
    const int e    = tid >> 6;       // candidate-block id (0..3)
    const int n    = rblk * 64 + rr; // row within patch

    // load patch features + inverse norms from scratch (coalesced)
    {
        const float4* gf4 = reinterpret_cast<const float4*>(g_feat + pp * 5120);
        float4* sa4 = reinterpret_cast<float4*>(accf);
        for (int idx = tid; idx < 1280; idx += 256) sa4[idx] = gf4[idx];
        if (tid < 256) {
            double v = g_invn[pp * 256 + tid];
            invd[tid] = v;
            invf[tid] = (float)v;
        }
    }
    __syncthreads();

    // ---- pass 1: row n vs candidates [e*64, e*64+64), packed top-16 ----
    {
        const float rin = invf[n];
        float rreg[18];
        const float* xr = accf + n * 20;
        #pragma unroll
        for (int d = 0; d < 18; ++d) rreg[d] = __fmul_rn(xr[d], rin);

        uint32_t kb[16];
        #pragma unroll
        for (int k = 0; k < 16; ++k) kb[k] = 0;

        const int mbase = e * 64;
        for (int mm = 0; mm < 64; ++mm) {
            const int m = mbase + mm;
            const float4* xm4 = reinterpret_cast<const float4*>(accf + m * 20);
            float4 v0 = xm4[0], v1 = xm4[1], v2 = xm4[2], v3 = xm4[3];  // broadcast
            float2 v4 = *reinterpret_cast<const float2*>(accf + m * 20 + 16);
            float s0 = 0.f, s1 = 0.f, s2 = 0.f, s3 = 0.f;
            s0 = __fmaf_rn(rreg[0],  v0.x, s0); s1 = __fmaf_rn(rreg[1],  v0.y, s1);
            s2 = __fmaf_rn(rreg[2],  v0.z, s2); s3 = __fmaf_rn(rreg[3],  v0.w, s3);
            s0 = __fmaf_rn(rreg[4],  v1.x, s0); s1 = __fmaf_rn(rreg[5],  v1.y, s1);
            s2 = __fmaf_rn(rreg[6],  v1.z, s2); s3 = __fmaf_rn(rreg[7],  v1.w, s3);
            s0 = __fmaf_rn(rreg[8],  v2.x, s0); s1 = __fmaf_rn(rreg[9],  v2.y, s1);
            s2 = __fmaf_rn(rreg[10], v2.z, s2); s3 = __fmaf_rn(rreg[11], v2.w, s3);
            s0 = __fmaf_rn(rreg[12], v3.x, s0); s1 = __fmaf_rn(rreg[13], v3.y, s1);
            s2 = __fmaf_rn(rreg[14], v3.z, s2); s3 = __fmaf_rn(rreg[15], v3.w, s3);
            s0 = __fmaf_rn(rreg[16], v4.x, s0); s1 = __fmaf_rn(rreg[17], v4.y, s1);
            float s = __fmul_rn(__fadd_rn(__fadd_rn(s0, s1), __fadd_rn(s2, s3)),
                                invf[m]);

            uint32_t key = (fmono(s) & 0xFFFFFF00u) | (uint32_t)(255 - m);
            if (key > kb[15]) {
                uint32_t v = key;
                #pragma unroll
                for (int k = 0; k < 16; ++k) {
                    uint32_t mx = (v > kb[k]) ? v : kb[k];
                    uint32_t mn = (v > kb[k]) ? kb[k] : v;
                    kb[k] = mx; v = mn;
                }
            }
        }
        uint32_t* br = bufU + e * (64 * 17) + rr * 17;
        #pragma unroll
        for (int k = 0; k < 16; ++k) br[k] = kb[k];
    }
    __syncthreads();

    // ---- stage A (e<2): merge blocks (2e,2e+1) -> top-16 into slot 2e ----
    if (e < 2) {
        const uint32_t* pa = bufU + (2 * e)     * (64 * 17) + rr * 17;
        const uint32_t* pb = bufU + (2 * e + 1) * (64 * 17) + rr * 17;
        uint32_t outk[16];
        int ia = 0, ib = 0;
        #pragma unroll
        for (int k = 0; k < 16; ++k) {          // ia,ib <= 15
            uint32_t va = pa[ia], vb = pb[ib];
            bool ta = (va >= vb);
            outk[k] = ta ? va : vb;
            ia += ta; ib += !ta;
        }
        uint32_t* po = bufU + (2 * e) * (64 * 17) + rr * 17;
        #pragma unroll
        for (int k = 0; k < 16; ++k) po[k] = outk[k];
    }
    __syncthreads();

    // ---- stage B (e==0): merge slots (0,2) -> 18-candidate superset ----
    if (e == 0) {
        const uint32_t* pa = bufU + 0 * (64 * 17) + rr * 17;
        const uint32_t* pb = bufU + 2 * (64 * 17) + rr * 17;
        uint8_t outc[18];
        int ia = 0, ib = 0;
        #pragma unroll
        for (int k = 0; k < 18; ++k) {
            uint32_t va = (ia < 16) ? pa[ia] : 0u;
            uint32_t vb = (ib < 16) ? pb[ib] : 0u;
            bool ta = (va >= vb);
            uint32_t v = ta ? va : vb;
            outc[k] = (uint8_t)(255u - (v & 0xFFu));
            ia += ta; ib += !ta;
        }
        uint8_t* cr = cand + rr * 20;
        #pragma unroll
        for (int k = 0; k < 18; ++k) cr[k] = outc[k];
    }
    __syncthreads();   // bufU dead; simk region live

    // ---- df64 rerank: candidates split 5/5/4/4 across e ----
    {
        float ra[20];
        {
            const float4* ar4 = reinterpret_cast<const float4*>(accf + n * 20);
            #pragma unroll
            for (int qq = 0; qq < 5; ++qq)
                reinterpret_cast<float4*>(ra)[qq] = ar4[qq];
        }
        const double inv_n = invd[n];
        const uint8_t* cr = cand + rr * 20;
        const int t0 = (e < 2) ? e * 5 : 10 + (e - 2) * 4;
        const int tn = (e < 2) ? 5 : 4;

        #pragma unroll 1
        for (int tt = 0; tt < 5; ++tt) {
            if (tt >= tn) break;             // uniform per warp (e fixed)
            const int t = t0 + tt;
            const int m = (int)cr[t];
            float am[20];
            {
                const float4* am4 = reinterpret_cast<const float4*>(accf + m * 20);
                #pragma unroll
                for (int qq = 0; qq < 5; ++qq)
                    reinterpret_cast<float4*>(am)[qq] = am4[qq];
            }
            // Dot2 (compensated fp32 dot)
            float sh = 0.0f, sl = 0.0f;
            #pragma unroll
            for (int d = 0; d < 18; ++d) {
                float av = ra[d], bv = am[d];
                float ph = __fmul_rn(av, bv);
                float pl = __fmaf_rn(av, bv, -ph);
                float t1 = __fadd_rn(sh, ph);
                float zz = __fsub_rn(t1, sh);
                float ee = __fadd_rn(__fsub_rn(sh, __fsub_rn(t1, zz)),
                                     __fsub_rn(ph, zz));
                sh = t1;
                sl = __fadd_rn(sl, __fadd_rn(ee, pl));
            }
            double sim = ((double)sh + (double)sl) * inv_n * invd[m];
            simk[rr * 18 + t] = (dmono(sim) & ~0xFFull) | (uint64_t)(255 - m);
        }
    }
    __syncthreads();

    // ---- top-15 select + sigmoid/softmax (e==0) ----
    if (e == 0) {
        const uint64_t* sr = simk + rr * 18;
        uint64_t top[K];
        #pragma unroll
        for (int k = 0; k < K; ++k) top[k] = 0;
        #pragma unroll
        for (int t = 0; t < 18; ++t) {
            uint64_t u = sr[t];
            if (u > top[K - 1]) {
                #pragma unroll
                for (int k = 0; k < K; ++k) {
                    uint64_t mx = (u > top[k]) ? u : top[k];
                    uint64_t mn = (u > top[k]) ? top[k] : u;
                    top[k] = mx; u = mn;
                }
            }
        }
        float sims[K]; int rows[K];
        #pragma unroll
        for (int k = 0; k < K; ++k) {
            rows[k] = 255 - (int)(top[k] & 0xFFull);
            sims[k] = (float)dunmono((top[k] & ~0xFFull) | 0x80ull);
        }

        const float alpha = edge_alpha[0];
        const float beta  = edge_beta[0];
        float wn_[K];
        float wmax = -1e30f;
        #pragma unroll
        for (int k = 0; k < K; ++k) {
            float z  = __fadd_rn(beta, __fmul_rn(alpha, sims[k]));
            float wv = __fdiv_rn(1.0f, __fadd_rn(1.0f, expf(-z)));
            wn_[k] = wv;
            wmax = fmaxf(wmax, wv);
        }
        float wsum = 0.0f;
        #pragma unroll
        for (int k = 0; k < K; ++k) {
            wn_[k] = expf(__fadd_rn(wn_[k], -wmax));
            wsum = __fadd_rn(wsum, wn_[k]);
        }
        float*         wp = g_w    + (pp * 256 + n) * 16;
        unsigned char* rp = g_rows + (pp * 256 + n) * 16;
        #pragma unroll
        for (int k = 0; k < K; ++k) {
            wp[k] = __fdiv_rn(wn_[k], wsum);
            rp[k] = (unsigned char)rows[k];
        }
        wp[15] = 0.f; rp[15] = 0;
    }
}

// ============================ K3: gather ===================================
constexpr int K3_OFF_XO  = 0;                       // 256*132*4 = 135168
constexpr int K3_OFF_WR  = 135168;                  // 256*16*4  = 16384
constexpr int K3_OFF_RW  = 151552;                  // 256*16    = 4096
constexpr int K3_OFF_STG = 155648;                  // 128*64*4  = 32768
constexpr int K3_SMEM = 188416;

__global__ void __launch_bounds__(1024, 1)
k3_gather(const float* __restrict__ x_in, float* __restrict__ out)
{
    extern __shared__ char smraw[];
    float*    xo = reinterpret_cast<float*>(smraw + K3_OFF_XO);   // [256][132]
    float*    wr = reinterpret_cast<float*>(smraw + K3_OFF_WR);   // [256][16]
    uint8_t*  rw = reinterpret_cast<uint8_t*>(smraw + K3_OFF_RW); // [256][16]
    float*    stg = reinterpret_cast<float*>(smraw + K3_OFF_STG); // [128][64]

    const int p   = blockIdx.x;
    const int b   = p / 49;
    const int wg  = (p / 7) % 7;
    const int hg  = p % 7;
    const int tid = threadIdx.x;
    const int gbase = ((b * C * 112) + wg * 16) * 112 + hg * 16;

    // load patch tile + weights/rows
    for (int idx = tid; idx < C * N; idx += 1024) {
        int c = idx >> 8;
        int nn = idx & 255;
        int i = nn >> 4, j = nn & 15;
        xo[nn * XO_PITCH + c] = x_in[gbase + c * 12544 + i * 112 + j];
    }
    for (int idx = tid; idx < 4096; idx += 1024) wr[idx] = g_w[p * 4096 + idx];
    {
        const uint32_t* gr32 = reinterpret_cast<const uint32_t*>(g_rows);
        uint32_t* rw32 = reinterpret_cast<uint32_t*>(rw);
        if (tid < 1024) rw32[tid] = gr32[p * 1024 + tid];
    }
    __syncthreads();

    const int wid  = tid >> 5;
    const int lane = tid & 31;
    const float4* xo4 = reinterpret_cast<const float4*>(xo);

    #pragma unroll 1
    for (int g = 0; g < 4; ++g) {
        #pragma unroll
        for (int px = 0; px < 2; ++px) {
            const int pl = wid * 2 + px;        // 0..63
            const int n2 = g * 64 + pl;
            const float*   wrow = wr + n2 * 16;
            const uint8_t* cr   = rw + n2 * 16;
            float4 o = make_float4(0.f, 0.f, 0.f, 0.f);
            #pragma unroll
            for (int k = 0; k < K; ++k) {
                const float wk  = wrow[k];                   // broadcast
                const int   row = (int)cr[k];                // broadcast
                float4 v = xo4[row * (XO_PITCH / 4) + lane]; // conflict-free
                o.x = __fmaf_rn(wk, v.x, o.x);
                o.y = __fmaf_rn(wk, v.y, o.y);
                o.z = __fmaf_rn(wk, v.z, o.z);
                o.w = __fmaf_rn(wk, v.w, o.w);
            }
            const int c0 = lane * 4;
            stg[stg_off(c0 + 0, pl)] = o.x;
            stg[stg_off(c0 + 1, pl)] = o.y;
            stg[stg_off(c0 + 2, pl)] = o.z;
            stg[stg_off(c0 + 3, pl)] = o.w;
        }
        __syncthreads();
        #pragma unroll
        for (int t = 0; t < 8; ++t) {
            const int idx = t * 1024 + tid;
            const int c  = idx >> 6;
            const int pl = idx & 63;
            const int n2 = g * 64 + pl;
            const int i = n2 >> 4, j = n2 & 15;
            out[gbase + c * 12544 + i * 112 + j] = stg[stg_off(c, pl)];
        }
        __syncthreads();
    }
}

// ============================ launch =======================================
extern "C" void kernel_launch(void* const* d_in, const int* in_sizes, int n_in,
                              void* d_out, int out_size) {
    const float* x_in = (const float*)d_in[0];
    const float* f_w  = (const float*)d_in[1];
    const float* f_b  = (const float*)d_in[2];
    const float* ea   = (const float*)d_in[3];
    const float* eb   = (const float*)d_in[4];
    float* out = (float*)d_out;

    cudaFuncSetAttribute(k1_features,
                         cudaFuncAttributeMaxDynamicSharedMemorySize, K1_SMEM);
    cudaFuncSetAttribute(k2_edges,
                         cudaFuncAttributeMaxDynamicSharedMemorySize, K2_SMEM);
    cudaFuncSetAttribute(k3_gather,
                         cudaFuncAttributeMaxDynamicSharedMemorySize, K3_SMEM);

    k1_features<<<784, 256, K1_SMEM>>>(x_in, f_w, f_b);
    k2_edges<<<784, 256, K2_SMEM>>>(ea, eb);
    k3_gather<<<196, 1024, K3_SMEM>>>(x_in, out);
}

// round 16
// speedup vs baseline: 1.2537x; 1.0981x over previous
#include <cuda_runtime.h>
#include <cstdint>

// Problem constants
constexpr int C  = 128;
constexpr int CF = 16;
constexpr int N  = 256;
constexpr int K  = 15;

// ---------------- global scratch (static __device__ — no runtime alloc) ----
__device__ float         g_feat[196 * 256 * 20];   // pre-norm feats (+grid, pads)
__device__ double        g_invn[196 * 256];        // fp64 1/norm
__device__ float         g_w   [196 * 256 * 16];   // softmax weights (15 + pad)
__device__ unsigned char g_rows[196 * 256 * 16];   // neighbor rows  (15 + pad)

// monotone float<->u32 (order-preserving)
__device__ __forceinline__ uint32_t fmono(float f) {
    uint32_t b = __float_as_uint(f);
    return (b & 0x80000000u) ? ~b : (b | 0x80000000u);
}
// monotone double<->u64
__device__ __forceinline__ uint64_t dmono(double d) {
    uint64_t b = (uint64_t)__double_as_longlong(d);
    return (b & 0x8000000000000000ull) ? ~b : (b | 0x8000000000000000ull);
}
__device__ __forceinline__ double dunmono(uint64_t u) {
    uint64_t b = (u & 0x8000000000000000ull) ? (u & 0x7FFFFFFFFFFFFFFFull) : ~u;
    return __longlong_as_double((long long)b);
}

// ============================ K1: features =================================
// grid 784 (quarter-patch = 64 pixels), TPB 256, 4 CTAs/SM.
// Channel-major smem tile: tile load = LDG.128 + STS.128 (no scalar LSU floor).
// Conv per-accumulator FMA order identical to R11-R15 (bitwise-identical).
constexpr int XC_PITCH  = 68;                       // 64 px + 4 pad (floats)
constexpr int K1_OFF_XC = 0;                        // 128*68*4 = 34816
constexpr int K1_OFF_FW = 34816;                    // 8192
constexpr int K1_OFF_FB = 43008;                    // 64
constexpr int K1_OFF_EX = 43072;                    // 64*20*4 = 5120 (pre-norm)
constexpr int K1_SMEM   = 48192;

__global__ void __launch_bounds__(256, 4)
k1_features(const float* __restrict__ x_in,
            const float* __restrict__ f_w,
            const float* __restrict__ f_b)
{
    extern __shared__ char smraw[];
    float* xc = reinterpret_cast<float*>(smraw + K1_OFF_XC);  // [128][68] ch-major
    float* fw = reinterpret_cast<float*>(smraw + K1_OFF_FW);  // [16][128]
    float* fb = reinterpret_cast<float*>(smraw + K1_OFF_FB);  // [16]
    float* ex = reinterpret_cast<float*>(smraw + K1_OFF_EX);  // [64][20] pre-norm

    const int pp   = blockIdx.x >> 2;   // patch
    const int rblk = blockIdx.x & 3;    // quarter (64 pixels)
    const int b   = pp / 49;
    const int wg  = (pp / 7) % 7;
    const int hg  = pp % 7;
    const int tid = threadIdx.x;
    const int nn  = tid & 63;           // local pixel 0..63
    const int q   = tid >> 6;           // channel quarter 0..3
    const int gbase = ((b * C * 112) + wg * 16) * 112 + hg * 16;

    // ---- weights (float4) + tile load (LDG.128 -> STS.128, conflict-free) ----
    {
        const float4* fw4g = reinterpret_cast<const float4*>(f_w);
        float4* fw4s = reinterpret_cast<float4*>(fw);
        for (int idx = tid; idx < CF * C / 4; idx += 256) fw4s[idx] = fw4g[idx];
        if (tid < CF) fb[tid] = f_b[tid];
    }
    {
        // 2048 float4s: idx -> (c = idx>>4, f4 = idx&15); px = f4*4 (4 consec j)
        #pragma unroll
        for (int k = 0; k < 8; ++k) {
            const int idx = k * 256 + tid;
            const int c  = idx >> 4;
            const int f4 = idx & 15;
            const int n  = rblk * 64 + f4 * 4;
            const int i  = n >> 4;
            const int j  = n & 15;
            float4 v = *reinterpret_cast<const float4*>(
                x_in + gbase + c * 12544 + i * 112 + j);
            *reinterpret_cast<float4*>(xc + c * XC_PITCH + f4 * 4) = v;
        }
    }
    __syncthreads();

    // ---- conv: thread (nn,q) computes channels q*4..q*4+3 ----
    // per accumulator: c ascending, FMA from 0, bias after (bitwise-identical)
    {
        float a0 = 0.f, a1 = 0.f, a2 = 0.f, a3 = 0.f;
        const float*  xcn = xc + nn;
        const float4* fw4 = reinterpret_cast<const float4*>(fw) + (q * 4) * 32;
        #pragma unroll 8
        for (int c4 = 0; c4 < 32; ++c4) {
            const float xv0 = xcn[(c4 * 4 + 0) * XC_PITCH];
            const float xv1 = xcn[(c4 * 4 + 1) * XC_PITCH];
            const float xv2 = xcn[(c4 * 4 + 2) * XC_PITCH];
            const float xv3 = xcn[(c4 * 4 + 3) * XC_PITCH];
            float4 w0 = fw4[c4];
            float4 w1 = fw4[32 + c4];
            float4 w2 = fw4[64 + c4];
            float4 w3 = fw4[96 + c4];
            a0 = __fmaf_rn(xv0, w0.x, a0); a0 = __fmaf_rn(xv1, w0.y, a0);
            a0 = __fmaf_rn(xv2, w0.z, a0); a0 = __fmaf_rn(xv3, w0.w, a0);
            a1 = __fmaf_rn(xv0, w1.x, a1); a1 = __fmaf_rn(xv1, w1.y, a1);
            a1 = __fmaf_rn(xv2, w1.z, a1); a1 = __fmaf_rn(xv3, w1.w, a1);
            a2 = __fmaf_rn(xv0, w2.x, a2); a2 = __fmaf_rn(xv1, w2.y, a2);
            a2 = __fmaf_rn(xv2, w2.z, a2); a2 = __fmaf_rn(xv3, w2.w, a2);
            a3 = __fmaf_rn(xv0, w3.x, a3); a3 = __fmaf_rn(xv1, w3.y, a3);
            a3 = __fmaf_rn(xv2, w3.z, a3); a3 = __fmaf_rn(xv3, w3.w, a3);
        }
        float4 o;
        o.x = __fadd_rn(a0, fb[q * 4 + 0]);
        o.y = __fadd_rn(a1, fb[q * 4 + 1]);
        o.z = __fadd_rn(a2, fb[q * 4 + 2]);
        o.w = __fadd_rn(a3, fb[q * 4 + 3]);
        *reinterpret_cast<float4*>(ex + nn * 20 + q * 4) = o;
    }
    __syncthreads();

    // ---- norm (q==0): fp64 1/sqrt via fp32-seeded Newton (2 iters) ----
    if (q == 0) {
        const int n = rblk * 64 + nn;
        const int i = n >> 4, j = n & 15;
        const float sd    = __fsqrt_rn(__fdiv_rn(5440.0f, 255.0f));
        const float denom = __fadd_rn(sd, 1e-5f);
        const float g0 = __fdiv_rn((float)i - 7.5f, denom);
        const float g1 = __fdiv_rn((float)j - 7.5f, denom);
        float* ar = ex + nn * 20;
        ar[16] = g0; ar[17] = g1; ar[18] = 0.f; ar[19] = 0.f;

        double ss = 0.0;                 // exact fp64 sum of fp32 squares
        #pragma unroll
        for (int d = 0; d < CF; ++d) ss = fma((double)ar[d], (double)ar[d], ss);
        ss = fma((double)g0, (double)g0, ss);
        ss = fma((double)g1, (double)g1, ss);

        double inv;
        if (ss > 1e-16) {
            double r = (double)rsqrtf((float)ss);
            const double hss = 0.5 * ss;
            r = r * fma(-hss, r * r, 1.5);
            r = r * fma(-hss, r * r, 1.5);
            inv = r;
        } else {
            inv = 1e8;
        }
        g_invn[pp * 256 + n] = inv;
    }
    __syncthreads();

    // ---- coalesced float4 flush of pre-norm feats to scratch ----
    {
        const float4* ex4 = reinterpret_cast<const float4*>(ex);
        float4* gf4 = reinterpret_cast<float4*>(g_feat) + pp * 1280 + rblk * 320;
        for (int idx = tid; idx < 320; idx += 256) gf4[idx] = ex4[idx];
    }
}

// ============================ K2: edges (unchanged from R15) ===============
constexpr int K2_OFF_ACC  = 0;                       // 256*20*4 = 20480
constexpr int K2_OFF_INV  = 20480;                   // 2048
constexpr int K2_OFF_INVF = 22528;                   // 1024
constexpr int K2_OFF_BUF  = 23552;                   // 4*64*17*4 = 17408
constexpr int K2_OFF_CAND = 40960;                   // 1280
constexpr int K2_SMEM     = 42240;

__global__ void __launch_bounds__(256, 4)
k2_edges(const float* __restrict__ edge_alpha,
         const float* __restrict__ edge_beta)
{
    extern __shared__ char smraw[];
    float*    accf = reinterpret_cast<float*>(smraw + K2_OFF_ACC);   // [256][20]
    double*   invd = reinterpret_cast<double*>(smraw + K2_OFF_INV);  // [256]
    float*    invf = reinterpret_cast<float*>(smraw + K2_OFF_INVF);  // [256]
    uint32_t* bufU = reinterpret_cast<uint32_t*>(smraw + K2_OFF_BUF);// [4][64][17]
    uint64_t* simk = reinterpret_cast<uint64_t*>(smraw + K2_OFF_BUF);// [64][18]
    uint8_t*  cand = reinterpret_cast<uint8_t*>(smraw + K2_OFF_CAND);// [64][20]

    const int pp   = blockIdx.x >> 2;
    const int rblk = blockIdx.x & 3;
    const int tid  = threadIdx.x;
    const int rr   = tid & 63;
    const int e    = tid >> 6;
    const int n    = rblk * 64 + rr;

    {
        const float4* gf4 = reinterpret_cast<const float4*>(g_feat + pp * 5120);
        float4* sa4 = reinterpret_cast<float4*>(accf);
        for (int idx = tid; idx < 1280; idx += 256) sa4[idx] = gf4[idx];
        if (tid < 256) {
            double v = g_invn[pp * 256 + tid];
            invd[tid] = v;
            invf[tid] = (float)v;
        }
    }
    __syncthreads();

    // ---- pass 1: row n vs candidates [e*64, e*64+64), packed top-16 ----
    {
        const float rin = invf[n];
        float rreg[18];
        const float* xr = accf + n * 20;
        #pragma unroll
        for (int d = 0; d < 18; ++d) rreg[d] = __fmul_rn(xr[d], rin);

        uint32_t kb[16];
        #pragma unroll
        for (int k = 0; k < 16; ++k) kb[k] = 0;

        const int mbase = e * 64;
        for (int mm = 0; mm < 64; ++mm) {
            const int m = mbase + mm;
            const float4* xm4 = reinterpret_cast<const float4*>(accf + m * 20);
            float4 v0 = xm4[0], v1 = xm4[1], v2 = xm4[2], v3 = xm4[3];
            float2 v4 = *reinterpret_cast<const float2*>(accf + m * 20 + 16);
            float s0 = 0.f, s1 = 0.f, s2 = 0.f, s3 = 0.f;
            s0 = __fmaf_rn(rreg[0],  v0.x, s0); s1 = __fmaf_rn(rreg[1],  v0.y, s1);
            s2 = __fmaf_rn(rreg[2],  v0.z, s2); s3 = __fmaf_rn(rreg[3],  v0.w, s3);
            s0 = __fmaf_rn(rreg[4],  v1.x, s0); s1 = __fmaf_rn(rreg[5],  v1.y, s1);
            s2 = __fmaf_rn(rreg[6],  v1.z, s2); s3 = __fmaf_rn(rreg[7],  v1.w, s3);
            s0 = __fmaf_rn(rreg[8],  v2.x, s0); s1 = __fmaf_rn(rreg[9],  v2.y, s1);
            s2 = __fmaf_rn(rreg[10], v2.z, s2); s3 = __fmaf_rn(rreg[11], v2.w, s3);
            s0 = __fmaf_rn(rreg[12], v3.x, s0); s1 = __fmaf_rn(rreg[13], v3.y, s1);
            s2 = __fmaf_rn(rreg[14], v3.z, s2); s3 = __fmaf_rn(rreg[15], v3.w, s3);
            s0 = __fmaf_rn(rreg[16], v4.x, s0); s1 = __fmaf_rn(rreg[17], v4.y, s1);
            float s = __fmul_rn(__fadd_rn(__fadd_rn(s0, s1), __fadd_rn(s2, s3)),
                                invf[m]);

            uint32_t key = (fmono(s) & 0xFFFFFF00u) | (uint32_t)(255 - m);
            if (key > kb[15]) {
                uint32_t v = key;
                #pragma unroll
                for (int k = 0; k < 16; ++k) {
                    uint32_t mx = (v > kb[k]) ? v : kb[k];
                    uint32_t mn = (v > kb[k]) ? kb[k] : v;
                    kb[k] = mx; v = mn;
                }
            }
        }
        uint32_t* br = bufU + e * (64 * 17) + rr * 17;
        #pragma unroll
        for (int k = 0; k < 16; ++k) br[k] = kb[k];
    }
    __syncthreads();

    if (e < 2) {
        const uint32_t* pa = bufU + (2 * e)     * (64 * 17) + rr * 17;
        const uint32_t* pb = bufU + (2 * e + 1) * (64 * 17) + rr * 17;
        uint32_t outk[16];
        int ia = 0, ib = 0;
        #pragma unroll
        for (int k = 0; k < 16; ++k) {
            uint32_t va = pa[ia], vb = pb[ib];
            bool ta = (va >= vb);
            outk[k] = ta ? va : vb;
            ia += ta; ib += !ta;
        }
        uint32_t* po = bufU + (2 * e) * (64 * 17) + rr * 17;
        #pragma unroll
        for (int k = 0; k < 16; ++k) po[k] = outk[k];
    }
    __syncthreads();

    if (e == 0) {
        const uint32_t* pa = bufU + 0 * (64 * 17) + rr * 17;
        const uint32_t* pb = bufU + 2 * (64 * 17) + rr * 17;
        uint8_t outc[18];
        int ia = 0, ib = 0;
        #pragma unroll
        for (int k = 0; k < 18; ++k) {
            uint32_t va = (ia < 16) ? pa[ia] : 0u;
            uint32_t vb = (ib < 16) ? pb[ib] : 0u;
            bool ta = (va >= vb);
            uint32_t v = ta ? va : vb;
            outc[k] = (uint8_t)(255u - (v & 0xFFu));
            ia += ta; ib += !ta;
        }
        uint8_t* cr = cand + rr * 20;
        #pragma unroll
        for (int k = 0; k < 18; ++k) cr[k] = outc[k];
    }
    __syncthreads();

    {
        float ra[20];
        {
            const float4* ar4 = reinterpret_cast<const float4*>(accf + n * 20);
            #pragma unroll
            for (int qq = 0; qq < 5; ++qq)
                reinterpret_cast<float4*>(ra)[qq] = ar4[qq];
        }
        const double inv_n = invd[n];
        const uint8_t* cr = cand + rr * 20;
        const int t0 = (e < 2) ? e * 5 : 10 + (e - 2) * 4;
        const int tn = (e < 2) ? 5 : 4;

        #pragma unroll 1
        for (int tt = 0; tt < 5; ++tt) {
            if (tt >= tn) break;
            const int t = t0 + tt;
            const int m = (int)cr[t];
            float am[20];
            {
                const float4* am4 = reinterpret_cast<const float4*>(accf + m * 20);
                #pragma unroll
                for (int qq = 0; qq < 5; ++qq)
                    reinterpret_cast<float4*>(am)[qq] = am4[qq];
            }
            float sh = 0.0f, sl = 0.0f;
            #pragma unroll
            for (int d = 0; d < 18; ++d) {
                float av = ra[d], bv = am[d];
                float ph = __fmul_rn(av, bv);
                float pl = __fmaf_rn(av, bv, -ph);
                float t1 = __fadd_rn(sh, ph);
                float zz = __fsub_rn(t1, sh);
                float ee = __fadd_rn(__fsub_rn(sh, __fsub_rn(t1, zz)),
                                     __fsub_rn(ph, zz));
                sh = t1;
                sl = __fadd_rn(sl, __fadd_rn(ee, pl));
            }
            double sim = ((double)sh + (double)sl) * inv_n * invd[m];
            simk[rr * 18 + t] = (dmono(sim) & ~0xFFull) | (uint64_t)(255 - m);
        }
    }
    __syncthreads();

    if (e == 0) {
        const uint64_t* sr = simk + rr * 18;
        uint64_t top[K];
        #pragma unroll
        for (int k = 0; k < K; ++k) top[k] = 0;
        #pragma unroll
        for (int t = 0; t < 18; ++t) {
            uint64_t u = sr[t];
            if (u > top[K - 1]) {
                #pragma unroll
                for (int k = 0; k < K; ++k) {
                    uint64_t mx = (u > top[k]) ? u : top[k];
                    uint64_t mn = (u > top[k]) ? top[k] : u;
                    top[k] = mx; u = mn;
                }
            }
        }
        float sims[K]; int rows[K];
        #pragma unroll
        for (int k = 0; k < K; ++k) {
            rows[k] = 255 - (int)(top[k] & 0xFFull);
            sims[k] = (float)dunmono((top[k] & ~0xFFull) | 0x80ull);
        }

        const float alpha = edge_alpha[0];
        const float beta  = edge_beta[0];
        float wn_[K];
        float wmax = -1e30f;
        #pragma unroll
        for (int k = 0; k < K; ++k) {
            float z  = __fadd_rn(beta, __fmul_rn(alpha, sims[k]));
            float wv = __fdiv_rn(1.0f, __fadd_rn(1.0f, expf(-z)));
            wn_[k] = wv;
            wmax = fmaxf(wmax, wv);
        }
        float wsum = 0.0f;
        #pragma unroll
        for (int k = 0; k < K; ++k) {
            wn_[k] = expf(__fadd_rn(wn_[k], -wmax));
            wsum = __fadd_rn(wsum, wn_[k]);
        }
        float*         wp = g_w    + (pp * 256 + n) * 16;
        unsigned char* rp = g_rows + (pp * 256 + n) * 16;
        #pragma unroll
        for (int k = 0; k < K; ++k) {
            wp[k] = __fdiv_rn(wn_[k], wsum);
            rp[k] = (unsigned char)rows[k];
        }
        wp[15] = 0.f; rp[15] = 0;
    }
}

// ============================ K3: gather ===================================
// grid 784 = (patch, channel-quarter), TPB 256, 64 KB smem -> 3 CTAs/SM.
// Pixel-major tile xo[256][36] (32 ch + pad); warp = 4 pixels x 8 quads:
// neighbor-row LDS.128 is exactly 4 phases (4 rows x 32 consecutive words).
// k-ascending FMA per channel preserved -> bitwise-identical output.
constexpr int XO3_PITCH  = 36;                      // floats (9 quads)
constexpr int K3_OFF_XO  = 0;                       // 256*36*4 = 36864
constexpr int K3_OFF_WR  = 36864;                   // 256*16*4 = 16384
constexpr int K3_OFF_RW  = 53248;                   // 256*16   = 4096
constexpr int K3_OFF_STG = 57344;                   // 32*64*4  = 8192
constexpr int K3_SMEM    = 65536;

__global__ void __launch_bounds__(256, 3)
k3_gather(const float* __restrict__ x_in, float* __restrict__ out)
{
    extern __shared__ char smraw[];
    float*   xo  = reinterpret_cast<float*>(smraw + K3_OFF_XO);  // [256][36]
    float*   wr  = reinterpret_cast<float*>(smraw + K3_OFF_WR);  // [256][16]
    uint8_t* rw  = reinterpret_cast<uint8_t*>(smraw + K3_OFF_RW);// [256][16]
    float*   stg = reinterpret_cast<float*>(smraw + K3_OFF_STG); // [32][64] swz

    const int pp = blockIdx.x >> 2;     // patch
    const int cq = blockIdx.x & 3;      // channel quarter
    const int cb = cq * 32;             // channel base
    const int b   = pp / 49;
    const int wg  = (pp / 7) % 7;
    const int hg  = pp % 7;
    const int tid = threadIdx.x;
    const int gbase = ((b * C * 112) + wg * 16) * 112 + hg * 16;

    // ---- tile load: LDG.128, scatter STS.32 (bank-safe bit-sliced map) ----
    // idx bits: [0:4)=c_lo, [4]=f4_lo, [5:10)=f4_hi, [10]=c_hi
    #pragma unroll
    for (int k = 0; k < 8; ++k) {
        const int idx = k * 256 + tid;
        const int c  = (idx & 15) | (((idx >> 10) & 1) << 4);     // 0..31
        const int f4 = ((idx >> 4) & 1) | (((idx >> 5) & 31) << 1); // 0..63
        const int px = f4 * 4;
        const int i = px >> 4, j = px & 15;
        float4 v = *reinterpret_cast<const float4*>(
            x_in + gbase + (cb + c) * 12544 + i * 112 + j);
        float* xp = xo + px * XO3_PITCH + c;
        xp[0]              = v.x;
        xp[XO3_PITCH]      = v.y;
        xp[2 * XO3_PITCH]  = v.z;
        xp[3 * XO3_PITCH]  = v.w;
    }
    // ---- weights/rows: vector copies (pitch 16 preserved) ----
    {
        const float4* gw4 = reinterpret_cast<const float4*>(g_w + pp * 4096);
        float4* wr4 = reinterpret_cast<float4*>(wr);
        #pragma unroll
        for (int k = 0; k < 4; ++k) wr4[k * 256 + tid] = gw4[k * 256 + tid];
        const uint4* gr4 = reinterpret_cast<const uint4*>(g_rows + pp * 4096);
        reinterpret_cast<uint4*>(rw)[tid] = gr4[tid];
    }
    __syncthreads();

    const int lane  = tid & 31;
    const int wid   = tid >> 5;        // 0..7
    const int pxsub = lane >> 3;       // 0..3 (pixel within 4-group)
    const int qd    = lane & 7;        // 0..7 (channel quad)
    const float4* xo4 = reinterpret_cast<const float4*>(xo);

    #pragma unroll 1
    for (int g = 0; g < 4; ++g) {
        // ---- gather 64 pixels: warp = 4 pixels x 8 quads per iteration ----
        #pragma unroll
        for (int it = 0; it < 2; ++it) {
            const int pxl = wid * 8 + it * 4;         // local 4-block base
            const int n2  = g * 64 + pxl + pxsub;     // pixel in patch
            float4 o = make_float4(0.f, 0.f, 0.f, 0.f);
            #pragma unroll
            for (int k = 0; k < K; ++k) {
                const float wk  = wr[n2 * 16 + k];
                const int   row = (int)rw[n2 * 16 + k];
                float4 v = xo4[row * 9 + qd];         // 4 rows x 8 quads: 4-phase
                o.x = __fmaf_rn(wk, v.x, o.x);
                o.y = __fmaf_rn(wk, v.y, o.y);
                o.z = __fmaf_rn(wk, v.z, o.z);
                o.w = __fmaf_rn(wk, v.w, o.w);
            }
            // staging write: conflict-free block-swizzle
            const int px4 = pxl >> 2;                 // 4-block id 0..15
            const int slot = ((px4 + qd) & 15) * 4 + pxsub;
            float* sp = stg + (qd * 4) * 64 + slot;
            sp[0]   = o.x;
            sp[64]  = o.y;
            sp[128] = o.z;
            sp[192] = o.w;
        }
        __syncthreads();
        // ---- coalesced store: thread reads swizzled float4, STG.128 ----
        #pragma unroll
        for (int t2 = 0; t2 < 2; ++t2) {
            const int idx = t2 * 256 + tid;           // 0..511
            const int c_l = idx >> 4;                 // 0..31
            const int px4 = idx & 15;                 // 0..15
            const float4* sp4 = reinterpret_cast<const float4*>(stg);
            float4 v = sp4[c_l * 16 + ((px4 + (c_l >> 2)) & 15)];
            const int n2 = g * 64 + px4 * 4;
            const int i = n2 >> 4, j = n2 & 15;
            *reinterpret_cast<float4*>(
                out + gbase + (cb + c_l) * 12544 + i * 112 + j) = v;
        }
        __syncthreads();
    }
}

// ============================ launch =======================================
extern "C" void kernel_launch(void* const* d_in, const int* in_sizes, int n_in,
                              void* d_out, int out_size) {
    const float* x_in = (const float*)d_in[0];
    const float* f_w  = (const float*)d_in[1];
    const float* f_b  = (const float*)d_in[2];
    const float* ea   = (const float*)d_in[3];
    const float* eb   = (const float*)d_in[4];
    float* out = (float*)d_out;

    cudaFuncSetAttribute(k1_features,
                         cudaFuncAttributeMaxDynamicSharedMemorySize, K1_SMEM);
    cudaFuncSetAttribute(k2_edges,
                         cudaFuncAttributeMaxDynamicSharedMemorySize, K2_SMEM);
    cudaFuncSetAttribute(k3_gather,
                         cudaFuncAttributeMaxDynamicSharedMemorySize, K3_SMEM);

    k1_features<<<784, 256, K1_SMEM>>>(x_in, f_w, f_b);
    k2_edges<<<784, 256, K2_SMEM>>>(ea, eb);
    k3_gather<<<784, 256, K3_SMEM>>>(x_in, out);
}